// round 2
// baseline (speedup 1.0000x reference)
#include <cuda_runtime.h>
#include <math_constants.h>

#define BB 8
#define NN 2048
#define KNN 20
#define EPSB 1e-5f

// ---------------- scratch (device globals; no allocation allowed) ----------
__device__ int      g_idx[BB*NN*KNN];
__device__ float    g_x1[BB*NN*64];
__device__ float    g_x2[BB*NN*64];
__device__ float    g_x3[BB*NN*64];
__device__ unsigned g_gmax[BB*1024];

__device__ __forceinline__ float lrelu(float z){ return z >= 0.f ? z : 0.2f*z; }
__device__ __forceinline__ unsigned fenc(float f){
    unsigned u = __float_as_uint(f);
    return (u & 0x80000000u) ? ~u : (u | 0x80000000u);
}
__device__ __forceinline__ float fdec(unsigned e){
    return (e & 0x80000000u) ? __uint_as_float(e ^ 0x80000000u) : __uint_as_float(~e);
}

// ---------------- kNN: per-batch 2048 pts in smem, top-20 insertion --------
// which: 0 -> x (stride 3, off 0), 1 -> g_x1[...,6:9], 2 -> g_x2[...,6:9]
__global__ __launch_bounds__(256) void knn_kernel(const float* __restrict__ x, int which)
{
    __shared__ float4 pts[NN];
    int b = blockIdx.x;
    const float* base;
    int stride;
    if (which == 0){ base = x    + (size_t)b*NN*3;       stride = 3;  }
    else if (which == 1){ base = g_x1 + (size_t)b*NN*64 + 6; stride = 64; }
    else {              base = g_x2 + (size_t)b*NN*64 + 6; stride = 64; }

    for (int j = threadIdx.x; j < NN; j += 256){
        float px = base[(size_t)j*stride + 0];
        float py = base[(size_t)j*stride + 1];
        float pz = base[(size_t)j*stride + 2];
        pts[j] = make_float4(px, py, pz, px*px + py*py + pz*pz);
    }
    __syncthreads();

    int i = blockIdx.y*256 + threadIdx.x;
    float4 q = pts[i];

    float bd[KNN]; int bi[KNN];
#pragma unroll
    for (int t = 0; t < KNN; t++){ bd[t] = -CUDART_INF_F; bi[t] = 0; }

#pragma unroll 4
    for (int j = 0; j < NN; j++){
        float4 p = pts[j];
        float nd = 2.f*(q.x*p.x + q.y*p.y + q.z*p.z) - q.w - p.w;
        if (nd > bd[KNN-1]){
            int t = KNN-1;
            while (t > 0 && bd[t-1] < nd){ bd[t] = bd[t-1]; bi[t] = bi[t-1]; t--; }
            bd[t] = nd; bi[t] = j;
        }
    }
    int* o = g_idx + ((size_t)b*NN + i)*KNN;
#pragma unroll
    for (int t = 0; t < KNN; t++) o[t] = bi[t];
}

// ---------------- Stage 1: edge(3) -> 64 -> 64 -> max ----------------------
// block = 320 thr, 4 points/block. thread = (k = tid/16, og = (tid%16)*4)
__global__ __launch_bounds__(320) void stage1_kernel(
    const float* __restrict__ x,
    const float* __restrict__ W1, const float* __restrict__ W2,
    const float* __restrict__ bng, const float* __restrict__ bnb,
    const float* __restrict__ bnm, const float* __restrict__ bnv)
{
    __shared__ float W1T[6*64];
    __shared__ float W2T[64*64];
    __shared__ float eS[KNN*8];
    __shared__ float h1S[KNN*64];
    __shared__ float h2S[KNN*64];

    int tid = threadIdx.x;
    for (int t = tid; t < 6*64; t += 320){ int o = t/6, c = t%6; W1T[c*64+o] = W1[t]; }
    for (int t = tid; t < 64*64; t += 320){ int o = t>>6, c = t&63; W2T[c*64+o] = W2[t]; }

    int k  = tid / 16;
    int og = (tid & 15) * 4;

    float s1[4], b1[4], s2[4], b2[4];
#pragma unroll
    for (int q = 0; q < 4; q++){
        int o = og + q;
        float r = rsqrtf(bnv[o] + EPSB);
        s1[q] = bng[o]*r; b1[q] = bnb[o] - bnm[o]*s1[q];
        r = rsqrtf(bnv[64+o] + EPSB);
        s2[q] = bng[64+o]*r; b2[q] = bnb[64+o] - bnm[64+o]*s2[q];
    }

    for (int p = 0; p < 4; p++){
        int pt = blockIdx.x*4 + p;
        int bb = pt >> 11, ii = pt & 2047;
        __syncthreads();
        if (tid < KNN){
            int j = g_idx[(size_t)pt*KNN + tid];
            const float* xb = x + (size_t)bb*NN*3;
            float cx = xb[ii*3+0], cy = xb[ii*3+1], cz = xb[ii*3+2];
            float nx = xb[(size_t)j*3+0], ny = xb[(size_t)j*3+1], nz = xb[(size_t)j*3+2];
            float* e = &eS[tid*8];
            e[0] = nx-cx; e[1] = ny-cy; e[2] = nz-cz;
            e[3] = cx;    e[4] = cy;    e[5] = cz;
        }
        __syncthreads();
        // conv1 (6 -> 64)
        {
            float a[4] = {0.f,0.f,0.f,0.f};
#pragma unroll
            for (int c = 0; c < 6; c++){
                float ev = eS[k*8 + c];
                float4 w = *(const float4*)&W1T[c*64 + og];
                a[0] = fmaf(ev, w.x, a[0]); a[1] = fmaf(ev, w.y, a[1]);
                a[2] = fmaf(ev, w.z, a[2]); a[3] = fmaf(ev, w.w, a[3]);
            }
#pragma unroll
            for (int q = 0; q < 4; q++)
                h1S[k*64 + og + q] = lrelu(a[q]*s1[q] + b1[q]);
        }
        __syncthreads();
        // conv2 (64 -> 64)
        {
            float a[4] = {0.f,0.f,0.f,0.f};
#pragma unroll 8
            for (int c = 0; c < 64; c++){
                float hv = h1S[k*64 + c];
                float4 w = *(const float4*)&W2T[c*64 + og];
                a[0] = fmaf(hv, w.x, a[0]); a[1] = fmaf(hv, w.y, a[1]);
                a[2] = fmaf(hv, w.z, a[2]); a[3] = fmaf(hv, w.w, a[3]);
            }
#pragma unroll
            for (int q = 0; q < 4; q++)
                h2S[k*64 + og + q] = lrelu(a[q]*s2[q] + b2[q]);
        }
        __syncthreads();
        if (tid < 64){
            float m = -CUDART_INF_F;
#pragma unroll
            for (int kk = 0; kk < KNN; kk++) m = fmaxf(m, h2S[kk*64 + tid]);
            g_x1[(size_t)pt*64 + tid] = m;
        }
    }
}

// ---------------- Stage 2/3: edge(64) -> 64 [-> 64] -> max -----------------
// SECOND=true : xin = g_x1, convs Wa,Wb, xout = g_x2   (stage 2)
// SECOND=false: xin = g_x2, conv Wa only, xout = g_x3  (stage 3)
// z[o] = sum_c nb[c]*Wa[o][c] + sum_c ctr[c]*(Wa[o][64+c]-Wa[o][c])
template<bool SECOND>
__global__ __launch_bounds__(320) void stage23_kernel(
    const float* __restrict__ Wa,    // (64,128)
    const float* __restrict__ Wb,    // (64,64) if SECOND
    const float* __restrict__ bng, const float* __restrict__ bnb,
    const float* __restrict__ bnm, const float* __restrict__ bnv)
{
    const float* __restrict__ xin  = SECOND ? g_x1 : g_x2;
    float*       __restrict__ xout = SECOND ? g_x2 : g_x3;

    __shared__ float WaT[64*64];
    __shared__ float WbT[SECOND ? 64*64 : 4];
    __shared__ float nbF[KNN*64];    // also reused as h2 buffer when SECOND
    __shared__ float h1S[KNN*64];
    __shared__ float ctrS[64];
    __shared__ float tS[64];

    int tid = threadIdx.x;
    for (int t = tid; t < 64*64; t += 320){ int o = t>>6, c = t&63; WaT[c*64+o] = Wa[o*128 + c]; }
    if (SECOND)
        for (int t = tid; t < 64*64; t += 320){ int o = t>>6, c = t&63; WbT[c*64+o] = Wb[t]; }

    int k  = tid / 16;
    int og = (tid & 15) * 4;

    float s1[4], b1[4], s2[4], b2[4];
#pragma unroll
    for (int q = 0; q < 4; q++){
        int o = og + q;
        float r = rsqrtf(bnv[o] + EPSB);
        s1[q] = bng[o]*r; b1[q] = bnb[o] - bnm[o]*s1[q];
        if (SECOND){
            r = rsqrtf(bnv[64+o] + EPSB);
            s2[q] = bng[64+o]*r; b2[q] = bnb[64+o] - bnm[64+o]*s2[q];
        }
    }

    for (int p = 0; p < 4; p++){
        int pt = blockIdx.x*4 + p;
        __syncthreads();
        if (tid < 64) ctrS[tid] = xin[(size_t)pt*64 + tid];
        for (int t = tid; t < KNN*64; t += 320){
            int kk = t >> 6, c = t & 63;
            int j = g_idx[(size_t)pt*KNN + kk];
            int bb = pt >> 11;
            nbF[t] = xin[((size_t)bb*NN + j)*64 + c];
        }
        __syncthreads();
        if (tid < 64){
            int o = tid;
            float acc = 0.f;
#pragma unroll 8
            for (int c = 0; c < 64; c++)
                acc = fmaf(ctrS[c], __ldg(&Wa[o*128 + 64 + c]) - __ldg(&Wa[o*128 + c]), acc);
            tS[o] = acc;
        }
        __syncthreads();
        // conv-a (128 -> 64), center term folded in
        {
            float4 t4 = *(const float4*)&tS[og];
            float a[4] = {t4.x, t4.y, t4.z, t4.w};
#pragma unroll 8
            for (int c = 0; c < 64; c++){
                float hv = nbF[k*64 + c];
                float4 w = *(const float4*)&WaT[c*64 + og];
                a[0] = fmaf(hv, w.x, a[0]); a[1] = fmaf(hv, w.y, a[1]);
                a[2] = fmaf(hv, w.z, a[2]); a[3] = fmaf(hv, w.w, a[3]);
            }
#pragma unroll
            for (int q = 0; q < 4; q++)
                h1S[k*64 + og + q] = lrelu(a[q]*s1[q] + b1[q]);
        }
        __syncthreads();
        if (SECOND){
            float a[4] = {0.f,0.f,0.f,0.f};
#pragma unroll 8
            for (int c = 0; c < 64; c++){
                float hv = h1S[k*64 + c];
                float4 w = *(const float4*)&WbT[c*64 + og];
                a[0] = fmaf(hv, w.x, a[0]); a[1] = fmaf(hv, w.y, a[1]);
                a[2] = fmaf(hv, w.z, a[2]); a[3] = fmaf(hv, w.w, a[3]);
            }
            __syncthreads();   // nbF reads in conv-a done; safe to overwrite
#pragma unroll
            for (int q = 0; q < 4; q++)
                nbF[k*64 + og + q] = lrelu(a[q]*s2[q] + b2[q]);
            __syncthreads();
            if (tid < 64){
                float m = -CUDART_INF_F;
#pragma unroll
                for (int kk = 0; kk < KNN; kk++) m = fmaxf(m, nbF[kk*64 + tid]);
                xout[(size_t)pt*64 + tid] = m;
            }
        } else {
            if (tid < 64){
                float m = -CUDART_INF_F;
#pragma unroll
                for (int kk = 0; kk < KNN; kk++) m = fmaxf(m, h1S[kk*64 + tid]);
                xout[(size_t)pt*64 + tid] = m;
            }
        }
    }
}

// ---------------- init / final GEMM / outputs ------------------------------
__global__ void init_gmax_kernel(){
    int t = blockIdx.x*256 + threadIdx.x;
    if (t < BB*1024) g_gmax[t] = 0u;
}

// 64x64 tile GEMM: (16384 x 192) @ W6^T (192 x 1024), fused BN+lrelu+max.
__global__ __launch_bounds__(256) void final_kernel(
    const float* __restrict__ W6,
    const float* __restrict__ bn6g, const float* __restrict__ bn6b,
    const float* __restrict__ bn6m, const float* __restrict__ bn6v)
{
    __shared__ float As[64*68];
    __shared__ float Bs[64*68];
    __shared__ float ss6[64], sb6[64];
    __shared__ float red[64*16];

    int tid = threadIdx.x;
    int m0 = blockIdx.x*64, n0 = blockIdx.y*64;
    int bb = m0 >> 11;

    if (tid < 64){
        int o = n0 + tid;
        float r = rsqrtf(bn6v[o] + EPSB);
        ss6[tid] = bn6g[o]*r; sb6[tid] = bn6b[o] - bn6m[o]*ss6[tid];
    }

    int tm = tid & 15, tn = tid >> 4;
    float acc[4][4];
#pragma unroll
    for (int i = 0; i < 4; i++)
#pragma unroll
        for (int j = 0; j < 4; j++) acc[i][j] = 0.f;

    for (int ch = 0; ch < 3; ch++){
        const float* src = (ch == 0) ? g_x1 : (ch == 1) ? g_x2 : g_x3;
        __syncthreads();
        for (int t = tid; t < 4096; t += 256){
            int m = t >> 6, c = t & 63;
            As[c*68 + m] = src[((size_t)(m0+m))*64 + c];
        }
        for (int t = tid; t < 4096; t += 256){
            int nn = t >> 6, c = t & 63;
            Bs[c*68 + nn] = W6[(size_t)(n0+nn)*192 + ch*64 + c];
        }
        __syncthreads();
#pragma unroll 8
        for (int c = 0; c < 64; c++){
            float4 a  = *(const float4*)&As[c*68 + tm*4];
            float4 bv = *(const float4*)&Bs[c*68 + tn*4];
            acc[0][0] = fmaf(a.x,bv.x,acc[0][0]); acc[0][1] = fmaf(a.x,bv.y,acc[0][1]);
            acc[0][2] = fmaf(a.x,bv.z,acc[0][2]); acc[0][3] = fmaf(a.x,bv.w,acc[0][3]);
            acc[1][0] = fmaf(a.y,bv.x,acc[1][0]); acc[1][1] = fmaf(a.y,bv.y,acc[1][1]);
            acc[1][2] = fmaf(a.y,bv.z,acc[1][2]); acc[1][3] = fmaf(a.y,bv.w,acc[1][3]);
            acc[2][0] = fmaf(a.z,bv.x,acc[2][0]); acc[2][1] = fmaf(a.z,bv.y,acc[2][1]);
            acc[2][2] = fmaf(a.z,bv.z,acc[2][2]); acc[2][3] = fmaf(a.z,bv.w,acc[2][3]);
            acc[3][0] = fmaf(a.w,bv.x,acc[3][0]); acc[3][1] = fmaf(a.w,bv.y,acc[3][1]);
            acc[3][2] = fmaf(a.w,bv.z,acc[3][2]); acc[3][3] = fmaf(a.w,bv.w,acc[3][3]);
        }
    }

    float zmax[4];
#pragma unroll
    for (int nq = 0; nq < 4; nq++){
        int nl = tn*4 + nq;
        float s = ss6[nl], bo = sb6[nl];
        float mx = -CUDART_INF_F;
#pragma unroll
        for (int mq = 0; mq < 4; mq++){
            float z = lrelu(fmaf(acc[mq][nq], s, bo));
            mx = fmaxf(mx, z);
        }
        zmax[nq] = mx;
    }
    __syncthreads();
#pragma unroll
    for (int nq = 0; nq < 4; nq++) red[(tn*4+nq)*16 + tm] = zmax[nq];
    __syncthreads();
    if (tid < 64){
        float mx = -CUDART_INF_F;
#pragma unroll
        for (int t = 0; t < 16; t++) mx = fmaxf(mx, red[tid*16 + t]);
        atomicMax(&g_gmax[bb*1024 + n0 + tid], fenc(mx));
    }
}

__global__ void feat_kernel(float* __restrict__ out){
    int t = blockIdx.x*256 + threadIdx.x;
    if (t < BB*1024) out[t] = fdec(g_gmax[t]);
}

// x4^T : out[8192 + b*192*2048 + c*2048 + n] = x4[b][n][c]
__global__ void x4t_kernel(float* __restrict__ out){
    int t = blockIdx.x*256 + threadIdx.x;
    if (t >= BB*192*NN) return;
    int n  = t & 2047;
    int c  = (t >> 11) % 192;
    int bb = t / (192*NN);
    const float* src = (c < 64) ? g_x1 : (c < 128) ? g_x2 : g_x3;
    int cc = c & 63;
    out[BB*1024 + t] = src[((size_t)bb*NN + n)*64 + cc];
}

// ---------------- launch ----------------------------------------------------
extern "C" void kernel_launch(void* const* d_in, const int* in_sizes, int n_in,
                              void* d_out, int out_size)
{
    const float* x    = (const float*)d_in[0];
    const float* W1   = (const float*)d_in[1];
    const float* W2   = (const float*)d_in[2];
    const float* W3   = (const float*)d_in[3];
    const float* W4   = (const float*)d_in[4];
    const float* W5   = (const float*)d_in[5];
    const float* W6   = (const float*)d_in[6];
    const float* bng  = (const float*)d_in[7];
    const float* bnb  = (const float*)d_in[8];
    const float* bnm  = (const float*)d_in[9];
    const float* bnv  = (const float*)d_in[10];
    const float* bn6g = (const float*)d_in[11];
    const float* bn6b = (const float*)d_in[12];
    const float* bn6m = (const float*)d_in[13];
    const float* bn6v = (const float*)d_in[14];
    float* out = (float*)d_out;

    init_gmax_kernel<<<32, 256>>>();

    // Stage 1
    knn_kernel<<<dim3(BB, NN/256), 256>>>(x, 0);
    stage1_kernel<<<BB*NN/4, 320>>>(x, W1, W2, bng, bnb, bnm, bnv);

    // Stage 2: kNN on x1[...,6:9], conv W3 then W4 (bn rows 2,3)
    knn_kernel<<<dim3(BB, NN/256), 256>>>(x, 1);
    stage23_kernel<true><<<BB*NN/4, 320>>>(W3, W4,
        bng + 2*64, bnb + 2*64, bnm + 2*64, bnv + 2*64);

    // Stage 3: kNN on x2[...,6:9], conv W5 only (bn row 4)
    knn_kernel<<<dim3(BB, NN/256), 256>>>(x, 2);
    stage23_kernel<false><<<BB*NN/4, 320>>>(W5, nullptr,
        bng + 4*64, bnb + 4*64, bnm + 4*64, bnv + 4*64);

    // Final block + global max pool
    final_kernel<<<dim3(BB*NN/64, 1024/64), 256>>>(W6, bn6g, bn6b, bn6m, bn6v);

    feat_kernel<<<32, 256>>>(out);
    x4t_kernel<<<(BB*192*NN + 255)/256, 256>>>(out);
}

// round 3
// speedup vs baseline: 1.0850x; 1.0850x over previous
#include <cuda_runtime.h>
#include <math_constants.h>

#define BB 8
#define NN 2048
#define KNN 20
#define NTOT (BB*NN)
#define EPSB 1e-5f

// ---------------- scratch (device globals; no allocation allowed) ----------
__device__ int      g_idx[NTOT*KNN];
__device__ float    g_x1[NTOT*64];
__device__ float    g_x2[NTOT*64];
__device__ float    g_x3[NTOT*64];
__device__ float    g_Y[NTOT*64];
__device__ float    g_T[NTOT*64];
__device__ unsigned g_gmax[BB*1024];

__device__ __forceinline__ float lrelu(float z){ return z >= 0.f ? z : 0.2f*z; }
__device__ __forceinline__ unsigned fenc(float f){
    unsigned u = __float_as_uint(f);
    return (u & 0x80000000u) ? ~u : (u | 0x80000000u);
}
__device__ __forceinline__ float fdec(unsigned e){
    return (e & 0x80000000u) ? __uint_as_float(e ^ 0x80000000u) : __uint_as_float(~e);
}

// ---------------- kNN (verified): per-batch pts in smem, top-20 insertion --
__global__ __launch_bounds__(256) void knn_kernel(const float* __restrict__ x, int which)
{
    __shared__ float4 pts[NN];
    int b = blockIdx.x;
    const float* base;
    int stride;
    if (which == 0){ base = x    + (size_t)b*NN*3;        stride = 3;  }
    else if (which == 1){ base = g_x1 + (size_t)b*NN*64 + 6; stride = 64; }
    else {               base = g_x2 + (size_t)b*NN*64 + 6; stride = 64; }

    for (int j = threadIdx.x; j < NN; j += 256){
        float px = base[(size_t)j*stride + 0];
        float py = base[(size_t)j*stride + 1];
        float pz = base[(size_t)j*stride + 2];
        pts[j] = make_float4(px, py, pz, px*px + py*py + pz*pz);
    }
    __syncthreads();

    int i = blockIdx.y*256 + threadIdx.x;
    float4 q = pts[i];

    float bd[KNN]; int bi[KNN];
#pragma unroll
    for (int t = 0; t < KNN; t++){ bd[t] = -CUDART_INF_F; bi[t] = 0; }

#pragma unroll 4
    for (int j = 0; j < NN; j++){
        float4 p = pts[j];
        float nd = 2.f*(q.x*p.x + q.y*p.y + q.z*p.z) - q.w - p.w;
        if (nd > bd[KNN-1]){
            int t = KNN-1;
            while (t > 0 && bd[t-1] < nd){ bd[t] = bd[t-1]; bi[t] = bi[t-1]; t--; }
            bd[t] = nd; bi[t] = j;
        }
    }
    int* o = g_idx + ((size_t)b*NN + i)*KNN;
#pragma unroll
    for (int t = 0; t < KNN; t++) o[t] = bi[t];
}

// ---------------- gemmYT: Y' = s*(x@Wlo^T), T' = s*(x@Wd^T)+b --------------
// W row layout: W[o][0..C-1] = lo (nb part), W[o][C..2C-1] = hi (ctr part).
// Wd = hi - lo.  SEL: 0 -> x arg, 1 -> g_x1, 2 -> g_x2.  32 points / block.
template<int C, int SEL>
__global__ __launch_bounds__(256) void gemmYT_kernel(
    const float* __restrict__ x, const float* __restrict__ W,
    const float* __restrict__ bng, const float* __restrict__ bnb,
    const float* __restrict__ bnm, const float* __restrict__ bnv)
{
    const float* __restrict__ xin = (SEL == 0) ? x : (SEL == 1) ? g_x1 : g_x2;

    __shared__ __align__(16) float Wlo[C*64];
    __shared__ __align__(16) float Wd [C*64];
    __shared__ __align__(16) float xS [32*C];

    int tid = threadIdx.x;
    int pt0 = blockIdx.x*32;

    for (int t = tid; t < C*64; t += 256){
        int o = t & 63, c = t >> 6;                 // conflict-free STS
        float lo = W[(size_t)o*(2*C) + c];
        Wlo[c*64 + o] = lo;
        Wd [c*64 + o] = W[(size_t)o*(2*C) + C + c] - lo;
    }
    for (int t = tid; t < 32*C; t += 256){
        int p = t / C, c = t % C;
        xS[p*C + c] = xin[((size_t)pt0 + p)*C + c];
    }

    int o = tid & 63;
    float s = bng[o]*rsqrtf(bnv[o] + EPSB);
    float b = bnb[o] - bnm[o]*s;
    __syncthreads();

#pragma unroll
    for (int i = 0; i < 8; i++){
        int p = (tid >> 6) + 4*i;
        float accY = 0.f, accT = 0.f;
#pragma unroll 8
        for (int c = 0; c < C; c++){
            float xv = xS[p*C + c];
            accY = fmaf(xv, Wlo[c*64 + o], accY);
            accT = fmaf(xv, Wd [c*64 + o], accT);
        }
        g_Y[((size_t)pt0 + p)*64 + o] = s*accY;
        g_T[((size_t)pt0 + p)*64 + o] = s*accT + b;
    }
}

// ---------------- edge_conv2: h1=lrelu(Y'[j]+T'[i]) tile -> conv-b -> k-max -
// 8 points (160 rows) per block, 512 threads, 5x4 register micro-tile.
// SEL_OUT: 1 -> g_x1, 2 -> g_x2.
template<int SEL_OUT>
__global__ __launch_bounds__(512) void edge_conv2_kernel(
    const float* __restrict__ Wb,
    const float* __restrict__ bng, const float* __restrict__ bnb,
    const float* __restrict__ bnm, const float* __restrict__ bnv)
{
    float* __restrict__ xout = (SEL_OUT == 1) ? g_x1 : g_x2;

    __shared__ __align__(16) float Ws[64*64];     // Ws[c*64+o] = Wb[o*64+c]
    __shared__ __align__(16) float As[64*161];    // As[c*161+r], r = row (pt,k)
    __shared__ __align__(16) float red[4*8*64];   // partial k-max [part][p][o]
    __shared__ int idxS[160];

    int tid = threadIdx.x;
    int pt0 = blockIdx.x*8;

    for (int t = tid; t < 4096; t += 512){
        int o = t & 63, c = t >> 6;                 // conflict-free STS
        Ws[c*64 + o] = Wb[(size_t)o*64 + c];
    }
    if (tid < 160) idxS[tid] = g_idx[(size_t)pt0*KNN + tid];
    __syncthreads();

    // build A tile: h1[r][c] = lrelu(Y'[nbr(r)][c] + T'[pt(r)][c])
    for (int e = tid; e < 160*64; e += 512){
        int r = e >> 6, c = e & 63;
        int p = r / KNN;
        int bb = (pt0 + p) >> 11;
        int j = idxS[r];
        float v = g_Y[((size_t)bb*NN + j)*64 + c] + g_T[((size_t)pt0 + p)*64 + c];
        As[c*161 + r] = lrelu(v);
    }

    int r5 = tid & 31;          // rows r5*5 .. r5*5+4 (all within one point)
    int tn = tid >> 5;          // cols tn*4 .. tn*4+3
    int o0 = tn*4;

    float s2[4], b2[4];
#pragma unroll
    for (int q = 0; q < 4; q++){
        int o = o0 + q;
        float r = rsqrtf(bnv[o] + EPSB);
        s2[q] = bng[o]*r; b2[q] = bnb[o] - bnm[o]*s2[q];
    }
    __syncthreads();

    float acc[5][4];
#pragma unroll
    for (int i = 0; i < 5; i++)
#pragma unroll
        for (int q = 0; q < 4; q++) acc[i][q] = 0.f;

#pragma unroll 4
    for (int c = 0; c < 64; c++){
        float4 w = *(const float4*)&Ws[c*64 + o0];   // warp-broadcast
        float a0 = As[c*161 + r5*5 + 0];
        float a1 = As[c*161 + r5*5 + 1];
        float a2 = As[c*161 + r5*5 + 2];
        float a3 = As[c*161 + r5*5 + 3];
        float a4 = As[c*161 + r5*5 + 4];
        acc[0][0]=fmaf(a0,w.x,acc[0][0]); acc[0][1]=fmaf(a0,w.y,acc[0][1]);
        acc[0][2]=fmaf(a0,w.z,acc[0][2]); acc[0][3]=fmaf(a0,w.w,acc[0][3]);
        acc[1][0]=fmaf(a1,w.x,acc[1][0]); acc[1][1]=fmaf(a1,w.y,acc[1][1]);
        acc[1][2]=fmaf(a1,w.z,acc[1][2]); acc[1][3]=fmaf(a1,w.w,acc[1][3]);
        acc[2][0]=fmaf(a2,w.x,acc[2][0]); acc[2][1]=fmaf(a2,w.y,acc[2][1]);
        acc[2][2]=fmaf(a2,w.z,acc[2][2]); acc[2][3]=fmaf(a2,w.w,acc[2][3]);
        acc[3][0]=fmaf(a3,w.x,acc[3][0]); acc[3][1]=fmaf(a3,w.y,acc[3][1]);
        acc[3][2]=fmaf(a3,w.z,acc[3][2]); acc[3][3]=fmaf(a3,w.w,acc[3][3]);
        acc[4][0]=fmaf(a4,w.x,acc[4][0]); acc[4][1]=fmaf(a4,w.y,acc[4][1]);
        acc[4][2]=fmaf(a4,w.z,acc[4][2]); acc[4][3]=fmaf(a4,w.w,acc[4][3]);
    }

    // per-thread partial k-max (5 of the 20 rows of point p)
    int p    = r5 >> 2;
    int part = r5 & 3;
#pragma unroll
    for (int q = 0; q < 4; q++){
        float mx = -CUDART_INF_F;
#pragma unroll
        for (int i = 0; i < 5; i++)
            mx = fmaxf(mx, lrelu(fmaf(acc[i][q], s2[q], b2[q])));
        red[(part*8 + p)*64 + o0 + q] = mx;
    }
    __syncthreads();

    {   // 512 threads = 8 points x 64 channels
        int pp = tid >> 6, oo = tid & 63;
        float m = red[(0*8 + pp)*64 + oo];
        m = fmaxf(m, red[(1*8 + pp)*64 + oo]);
        m = fmaxf(m, red[(2*8 + pp)*64 + oo]);
        m = fmaxf(m, red[(3*8 + pp)*64 + oo]);
        xout[((size_t)pt0 + pp)*64 + oo] = m;
    }
}

// ---------------- edge_max (stage 3): x3 = max_k lrelu(Y'[j]+T'[i]) --------
__global__ __launch_bounds__(256) void edge_max_kernel()
{
    __shared__ int idxS[4*KNN];
    int tid = threadIdx.x;
    int pt0 = blockIdx.x*4;
    if (tid < 4*KNN) idxS[tid] = g_idx[(size_t)pt0*KNN + tid];
    __syncthreads();

    int p = tid >> 6, o = tid & 63;
    int pt = pt0 + p;
    int bb = pt >> 11;
    float tv = g_T[(size_t)pt*64 + o];
    float m = -CUDART_INF_F;
#pragma unroll
    for (int k = 0; k < KNN; k++){
        int j = idxS[p*KNN + k];
        m = fmaxf(m, lrelu(g_Y[((size_t)bb*NN + j)*64 + o] + tv));
    }
    g_x3[(size_t)pt*64 + o] = m;
}

// ---------------- init / final GEMM / outputs (verified) -------------------
__global__ void init_gmax_kernel(){
    int t = blockIdx.x*256 + threadIdx.x;
    if (t < BB*1024) g_gmax[t] = 0u;
}

__global__ __launch_bounds__(256) void final_kernel(
    const float* __restrict__ W6,
    const float* __restrict__ bn6g, const float* __restrict__ bn6b,
    const float* __restrict__ bn6m, const float* __restrict__ bn6v)
{
    __shared__ float As[64*68];
    __shared__ float Bs[64*68];
    __shared__ float ss6[64], sb6[64];
    __shared__ float red[64*16];

    int tid = threadIdx.x;
    int m0 = blockIdx.x*64, n0 = blockIdx.y*64;
    int bb = m0 >> 11;

    if (tid < 64){
        int o = n0 + tid;
        float r = rsqrtf(bn6v[o] + EPSB);
        ss6[tid] = bn6g[o]*r; sb6[tid] = bn6b[o] - bn6m[o]*ss6[tid];
    }

    int tm = tid & 15, tn = tid >> 4;
    float acc[4][4];
#pragma unroll
    for (int i = 0; i < 4; i++)
#pragma unroll
        for (int j = 0; j < 4; j++) acc[i][j] = 0.f;

    for (int ch = 0; ch < 3; ch++){
        const float* src = (ch == 0) ? g_x1 : (ch == 1) ? g_x2 : g_x3;
        __syncthreads();
        for (int t = tid; t < 4096; t += 256){
            int m = t >> 6, c = t & 63;
            As[c*68 + m] = src[((size_t)(m0+m))*64 + c];
        }
        for (int t = tid; t < 4096; t += 256){
            int nn = t >> 6, c = t & 63;
            Bs[c*68 + nn] = W6[(size_t)(n0+nn)*192 + ch*64 + c];
        }
        __syncthreads();
#pragma unroll 8
        for (int c = 0; c < 64; c++){
            float4 a  = *(const float4*)&As[c*68 + tm*4];
            float4 bv = *(const float4*)&Bs[c*68 + tn*4];
            acc[0][0] = fmaf(a.x,bv.x,acc[0][0]); acc[0][1] = fmaf(a.x,bv.y,acc[0][1]);
            acc[0][2] = fmaf(a.x,bv.z,acc[0][2]); acc[0][3] = fmaf(a.x,bv.w,acc[0][3]);
            acc[1][0] = fmaf(a.y,bv.x,acc[1][0]); acc[1][1] = fmaf(a.y,bv.y,acc[1][1]);
            acc[1][2] = fmaf(a.y,bv.z,acc[1][2]); acc[1][3] = fmaf(a.y,bv.w,acc[1][3]);
            acc[2][0] = fmaf(a.z,bv.x,acc[2][0]); acc[2][1] = fmaf(a.z,bv.y,acc[2][1]);
            acc[2][2] = fmaf(a.z,bv.z,acc[2][2]); acc[2][3] = fmaf(a.z,bv.w,acc[2][3]);
            acc[3][0] = fmaf(a.w,bv.x,acc[3][0]); acc[3][1] = fmaf(a.w,bv.y,acc[3][1]);
            acc[3][2] = fmaf(a.w,bv.z,acc[3][2]); acc[3][3] = fmaf(a.w,bv.w,acc[3][3]);
        }
    }

    float zmax[4];
#pragma unroll
    for (int nq = 0; nq < 4; nq++){
        int nl = tn*4 + nq;
        float s = ss6[nl], bo = sb6[nl];
        float mx = -CUDART_INF_F;
#pragma unroll
        for (int mq = 0; mq < 4; mq++){
            float z = lrelu(fmaf(acc[mq][nq], s, bo));
            mx = fmaxf(mx, z);
        }
        zmax[nq] = mx;
    }
    __syncthreads();
#pragma unroll
    for (int nq = 0; nq < 4; nq++) red[(tn*4+nq)*16 + tm] = zmax[nq];
    __syncthreads();
    if (tid < 64){
        float mx = -CUDART_INF_F;
#pragma unroll
        for (int t = 0; t < 16; t++) mx = fmaxf(mx, red[tid*16 + t]);
        atomicMax(&g_gmax[bb*1024 + n0 + tid], fenc(mx));
    }
}

__global__ void feat_kernel(float* __restrict__ out){
    int t = blockIdx.x*256 + threadIdx.x;
    if (t < BB*1024) out[t] = fdec(g_gmax[t]);
}

__global__ void x4t_kernel(float* __restrict__ out){
    int t = blockIdx.x*256 + threadIdx.x;
    if (t >= BB*192*NN) return;
    int n  = t & 2047;
    int c  = (t >> 11) % 192;
    int bb = t / (192*NN);
    const float* src = (c < 64) ? g_x1 : (c < 128) ? g_x2 : g_x3;
    int cc = c & 63;
    out[BB*1024 + t] = src[((size_t)bb*NN + n)*64 + cc];
}

// ---------------- launch ----------------------------------------------------
extern "C" void kernel_launch(void* const* d_in, const int* in_sizes, int n_in,
                              void* d_out, int out_size)
{
    const float* x    = (const float*)d_in[0];
    const float* W1   = (const float*)d_in[1];
    const float* W2   = (const float*)d_in[2];
    const float* W3   = (const float*)d_in[3];
    const float* W4   = (const float*)d_in[4];
    const float* W5   = (const float*)d_in[5];
    const float* W6   = (const float*)d_in[6];
    const float* bng  = (const float*)d_in[7];
    const float* bnb  = (const float*)d_in[8];
    const float* bnm  = (const float*)d_in[9];
    const float* bnv  = (const float*)d_in[10];
    const float* bn6g = (const float*)d_in[11];
    const float* bn6b = (const float*)d_in[12];
    const float* bn6m = (const float*)d_in[13];
    const float* bn6v = (const float*)d_in[14];
    float* out = (float*)d_out;

    init_gmax_kernel<<<32, 256>>>();

    // Stage 1: knn(x) -> Y/T via W1 (bn row0) -> conv W2 (bn row1) -> x1
    knn_kernel<<<dim3(BB, NN/256), 256>>>(x, 0);
    gemmYT_kernel<3,0><<<NTOT/32, 256>>>(x, W1, bng, bnb, bnm, bnv);
    edge_conv2_kernel<1><<<NTOT/8, 512>>>(W2, bng+64, bnb+64, bnm+64, bnv+64);

    // Stage 2: knn(x1[6:9]) -> Y/T via W3 (row2) -> conv W4 (row3) -> x2
    knn_kernel<<<dim3(BB, NN/256), 256>>>(x, 1);
    gemmYT_kernel<64,1><<<NTOT/32, 256>>>(x, W3, bng+2*64, bnb+2*64, bnm+2*64, bnv+2*64);
    edge_conv2_kernel<2><<<NTOT/8, 512>>>(W4, bng+3*64, bnb+3*64, bnm+3*64, bnv+3*64);

    // Stage 3: knn(x2[6:9]) -> Y/T via W5 (row4) -> max -> x3
    knn_kernel<<<dim3(BB, NN/256), 256>>>(x, 2);
    gemmYT_kernel<64,2><<<NTOT/32, 256>>>(x, W5, bng+4*64, bnb+4*64, bnm+4*64, bnv+4*64);
    edge_max_kernel<<<NTOT/4, 256>>>();

    // Final block + global max pool
    final_kernel<<<dim3(NTOT/64, 1024/64), 256>>>(W6, bn6g, bn6b, bn6m, bn6v);

    feat_kernel<<<32, 256>>>(out);
    x4t_kernel<<<(BB*192*NN + 255)/256, 256>>>(out);
}